// round 13
// baseline (speedup 1.0000x reference)
#include <cuda_runtime.h>

// QPIELayer single-kernel version. 16-qubit circuit reduced to 10 live qubits
// (8 system + 2 ancilla); records are write-once / read-once-as-control and
// traced by the diagonal measurement, so each layer boundary is an incoherent
// 4-way branch split. 256 CTAs = one per (batch, layer1-branch, layer2-branch)
// leaf; each CTA redundantly recomputes layers 0/1 for its branch path
// entirely in shared memory (redundancy is free — the chip would be idle
// otherwise), then the last CTA per batch reduces the 16 branch partials.
//
// Bit layout: bits 0..7 = system qubits, bit 8 = ancilla 0, bit 9 = ancilla 1.
// State = 1024 float2 in shared memory, XOR-swizzled against bank conflicts.

#define NTH 256

__device__ float        g_ev[256 * 8];   // per (batch,branch-leaf) EV partials
__device__ unsigned int g_tk[16];        // per-batch monotonic arrival tickets

__device__ __forceinline__ int IDX(int i) { return i ^ ((i >> 5) & 31); }

__device__ __forceinline__ float2 cmul(float2 a, float2 b) {
    return make_float2(a.x * b.x - a.y * b.y, a.x * b.y + a.y * b.x);
}
__device__ __forceinline__ float2 cmac(float2 a, float2 b, float2 c) {   // a*b + c
    return make_float2(fmaf(a.x, b.x, fmaf(-a.y, b.y, c.x)),
                       fmaf(a.x, b.y, fmaf( a.y, b.x, c.y)));
}
__device__ __forceinline__ float2 cconj(float2 a) { return make_float2(a.x, -a.y); }
__device__ __forceinline__ float2 cadd(float2 a, float2 b) { return make_float2(a.x + b.x, a.y + b.y); }
__device__ __forceinline__ float2 csub(float2 a, float2 b) { return make_float2(a.x - b.x, a.y - b.y); }
__device__ __forceinline__ float2 chalf(float2 a) { return make_float2(0.5f * a.x, 0.5f * a.y); }

// ---- fused two-single-qubit-gates pass: U_b2 (x) U_b1 on quads -------------
template<int B1, int B2>
__device__ __forceinline__ void gate2(float2* st, const float2* Ua, const float2* Ub) {
    const int p = threadIdx.x;                       // exactly 256 quads
    const int m1 = (1 << B1) - 1, m2 = (1 << B2) - 1;
    int t   = ((p >> B1) << (B1 + 1)) | (p & m1);
    int i00 = ((t >> B2) << (B2 + 1)) | (t & m2);
    int i01 = i00 | (1 << B1), i10 = i00 | (1 << B2), i11 = i01 | (1 << B2);
    float2 x00 = st[IDX(i00)], x01 = st[IDX(i01)];
    float2 x10 = st[IDX(i10)], x11 = st[IDX(i11)];
    float2 y00 = cmac(Ua[0], x00, cmul(Ua[1], x01));
    float2 y01 = cmac(Ua[2], x00, cmul(Ua[3], x01));
    float2 y10 = cmac(Ua[0], x10, cmul(Ua[1], x11));
    float2 y11 = cmac(Ua[2], x10, cmul(Ua[3], x11));
    float2 z00 = cmac(Ub[0], y00, cmul(Ub[1], y10));
    float2 z10 = cmac(Ub[2], y00, cmul(Ub[3], y10));
    float2 z01 = cmac(Ub[0], y01, cmul(Ub[1], y11));
    float2 z11 = cmac(Ub[2], y01, cmul(Ub[3], y11));
    st[IDX(i00)] = z00; st[IDX(i01)] = z01; st[IDX(i10)] = z10; st[IDX(i11)] = z11;
    __syncthreads();
}

// ---- fused RZZ*RYY*RXX on (B1,B2), optionally followed by CCRX(anc=CC, B1, B2)
template<int B1, int B2, int CC>
__device__ __forceinline__ void pairGate(float2* st, const float* pc) {
    const float K = pc[0], Lc = pc[1], K2 = pc[2], L2 = pc[3], ec = pc[4], es = pc[5];
    const float2 e3 = make_float2(ec, -es), f3 = make_float2(ec, es);
    const int p = threadIdx.x;
    const int m1 = (1 << B1) - 1, m2 = (1 << B2) - 1;
    int t   = ((p >> B1) << (B1 + 1)) | (p & m1);
    int i00 = ((t >> B2) << (B2 + 1)) | (t & m2);
    int i01 = i00 | (1 << B1), i10 = i00 | (1 << B2), i11 = i01 | (1 << B2);
    float2 a00 = st[IDX(i00)], a01 = st[IDX(i01)];
    float2 a10 = st[IDX(i10)], a11 = st[IDX(i11)];
    float2 t00 = make_float2(K * a00.x - Lc * a11.y, K * a00.y + Lc * a11.x);
    float2 t11 = make_float2(K * a11.x - Lc * a00.y, K * a11.y + Lc * a00.x);
    float2 t01 = make_float2(K2 * a01.x + L2 * a10.y, K2 * a01.y - L2 * a10.x);
    float2 t10 = make_float2(K2 * a10.x + L2 * a01.y, K2 * a10.y - L2 * a01.x);
    float2 o00 = cmul(e3, t00), o11 = cmul(e3, t11);
    float2 o01 = cmul(f3, t01), o10 = cmul(f3, t10);
    if (CC >= 0 && ((i00 >> CC) & 1)) {
        const float cc = 0.92387953251128675613f;   // cos(pi/8)
        const float ss = 0.38268343236508977173f;   // sin(pi/8)
        float2 n01 = make_float2(cc * o01.x + ss * o11.y, cc * o01.y - ss * o11.x);
        float2 n11 = make_float2(cc * o11.x + ss * o01.y, cc * o11.y - ss * o01.x);
        o01 = n01; o11 = n11;
    }
    st[IDX(i00)] = o00; st[IDX(i01)] = o01; st[IDX(i10)] = o10; st[IDX(i11)] = o11;
    __syncthreads();
}

// ---- fused ancilla block: (H(x)H) then CRZ diagonal (then H(x)H if ODD) ----
template<int ODD>
__device__ __forceinline__ void ancBlock(float2* st, const float* pwh) {
    const int s = threadIdx.x;                       // 256 system states
    float2 x0 = st[IDX(s)],       x1 = st[IDX(s + 256)];
    float2 x2 = st[IDX(s + 512)], x3 = st[IDX(s + 768)];
    float2 v0 = chalf(cadd(cadd(x0, x1), cadd(x2, x3)));
    float2 v1 = chalf(cadd(csub(x0, x1), csub(x2, x3)));
    float2 v2 = chalf(csub(cadd(x0, x1), cadd(x2, x3)));
    float2 v3 = chalf(cadd(csub(x0, x1), csub(x3, x2)));
    float d0 = 0.0f, d1 = 0.0f;
#pragma unroll
    for (int j = 0; j < 8; ++j)
        if ((s >> j) & 1) { d0 += pwh[j]; d1 += pwh[8 + j]; }
    float sp, cp, sm, cm;
    sincosf(d0 + d1, &sp, &cp);
    sincosf(d0 - d1, &sm, &cm);
    float2 P = make_float2(cp, sp), M = make_float2(cm, sm);
    float2 w0 = cmul(cconj(P), v0);
    float2 w1 = cmul(M,        v1);
    float2 w2 = cmul(cconj(M), v2);
    float2 w3 = cmul(P,        v3);
    if (ODD) {
        float2 y0 = chalf(cadd(cadd(w0, w1), cadd(w2, w3)));
        float2 y1 = chalf(cadd(csub(w0, w1), csub(w2, w3)));
        float2 y2 = chalf(csub(cadd(w0, w1), cadd(w2, w3)));
        float2 y3 = chalf(cadd(csub(w0, w1), csub(w3, w2)));
        w0 = y0; w1 = y1; w2 = y2; w3 = y3;
    }
    st[IDX(s)] = w0; st[IDX(s + 256)] = w1; st[IDX(s + 512)] = w2; st[IDX(s + 768)] = w3;
    __syncthreads();
}

// ---- one full layer on a 1024-amp state ------------------------------------
template<int L>
__device__ __forceinline__ void simLayer(float2* st, const float* x, int batch,
                                         const float* w, const float* pw,
                                         float2 (*rotU)[4], float2 (*vwU)[4],
                                         float (*pco)[6], float* pwh) {
    const float* wl  = w  + L * 48;
    const float* pwl = pw + L * 16;
    const int tid = threadIdx.x;
    const float R = 0.70710678118654752440f;

    if (tid < 8) {                                   // per-qubit rot (RY even / RX odd)
        float s, c;
        sincosf(0.5f * x[batch * 8 + tid], &s, &c);
        float2 u00, u01, u10, u11;
        if ((L & 1) == 0) {
            u00 = make_float2(c, 0); u01 = make_float2(-s, 0);
            u10 = make_float2(s, 0); u11 = make_float2(c, 0);
        } else {
            u00 = make_float2(c, 0); u01 = make_float2(0, -s);
            u10 = make_float2(0, -s); u11 = make_float2(c, 0);
        }
        if (L == 0) {   // fold initial H: U <- U @ H
            float2 v00 = make_float2(R * (u00.x + u01.x), R * (u00.y + u01.y));
            float2 v01 = make_float2(R * (u00.x - u01.x), R * (u00.y - u01.y));
            float2 v10 = make_float2(R * (u10.x + u11.x), R * (u10.y + u11.y));
            float2 v11 = make_float2(R * (u10.x - u11.x), R * (u10.y - u11.y));
            u00 = v00; u01 = v01; u10 = v10; u11 = v11;
        }
        rotU[tid][0] = u00; rotU[tid][1] = u01; rotU[tid][2] = u10; rotU[tid][3] = u11;
    } else if (tid < 16) {                           // fused RZ*RY*RX (vw block)
        int q = tid - 8;
        float t1 = wl[24 + 3 * q], t2 = wl[25 + 3 * q], t3 = wl[26 + 3 * q];
        float s1, c1, s2, c2, es, ec;
        sincosf(0.5f * t1, &s1, &c1);
        sincosf(0.5f * t2, &s2, &c2);
        sincosf(0.5f * t3, &es, &ec);
        float2 a00 = make_float2(c1 * c2,  s1 * s2);
        float2 a01 = make_float2(-s2 * c1, -c2 * s1);
        float2 a10 = make_float2( s2 * c1, -c2 * s1);
        float2 a11 = make_float2(c1 * c2, -s1 * s2);
        float2 e = make_float2(ec, -es);
        vwU[q][0] = cmul(e, a00); vwU[q][1] = cmul(e, a01);
        vwU[q][2] = cmul(cconj(e), a10); vwU[q][3] = cmul(cconj(e), a11);
    } else if (tid < 23) {                           // pair-gate coefficients
        int i = tid - 16;
        float t1 = wl[3 * i], t2 = wl[3 * i + 1], t3 = wl[3 * i + 2];
        float sd, cd, s2, c2, es, ec;
        sincosf(0.5f * (t1 - t2), &sd, &cd);
        sincosf(0.5f * (t1 + t2), &s2, &c2);
        sincosf(0.5f * t3, &es, &ec);
        pco[i][0] = cd; pco[i][1] = -sd; pco[i][2] = c2; pco[i][3] = s2;
        pco[i][4] = ec; pco[i][5] = es;
    } else if (tid >= 32 && tid < 48) {
        pwh[tid - 32] = 0.5f * pwl[tid - 32];
    }
    __syncthreads();

    gate2<0, 1>(st, rotU[0], rotU[1]);
    gate2<2, 3>(st, rotU[2], rotU[3]);
    gate2<4, 5>(st, rotU[4], rotU[5]);
    gate2<6, 7>(st, rotU[6], rotU[7]);
    ancBlock<(L & 1)>(st, pwh);
    pairGate<0, 1, 8>(st, pco[0]);
    pairGate<2, 3, 9>(st, pco[1]);
    pairGate<4, 5, -1>(st, pco[2]);
    pairGate<6, 7, -1>(st, pco[3]);
    pairGate<1, 2, -1>(st, pco[4]);
    pairGate<3, 4, -1>(st, pco[5]);
    pairGate<5, 6, -1>(st, pco[6]);
    gate2<0, 1>(st, vwU[0], vwU[1]);
    gate2<2, 3>(st, vwU[2], vwU[3]);
    gate2<4, 5>(st, vwU[4], vwU[5]);
    gate2<6, 7>(st, vwU[6], vwU[7]);
}

// ---- branch compaction: keep ancilla pattern `br`, reset ancillas to |00> --
__device__ __forceinline__ void compact(float2* st, int br) {
    const int tid = threadIdx.x;
    float2 v = st[IDX(br * 256 + tid)];
    __syncthreads();
    st[IDX(tid)]       = v;
    st[IDX(tid + 256)] = make_float2(0, 0);
    st[IDX(tid + 512)] = make_float2(0, 0);
    st[IDX(tid + 768)] = make_float2(0, 0);
    __syncthreads();
}

__global__ void __launch_bounds__(NTH)
qpie_all(const float* __restrict__ x, const float* __restrict__ w,
         const float* __restrict__ pw, float* __restrict__ out) {
    __shared__ float2 st[1024];
    __shared__ float2 rotU[8][4];
    __shared__ float2 vwU[8][4];
    __shared__ float  pco[7][6];
    __shared__ float  pwh[16];
    __shared__ float  wsum[NTH / 32][8];
    __shared__ unsigned int lastflag;

    const int blk = blockIdx.x, tid = threadIdx.x;
    const int batch = blk >> 4, br1 = (blk >> 2) & 3, br2 = blk & 3;

    for (int i = tid; i < 1024; i += NTH)
        st[i] = make_float2(i == 0 ? 1.0f : 0.0f, 0.0f);     // IDX(0)==0
    __syncthreads();

    simLayer<0>(st, x, batch, w, pw, rotU, vwU, pco, pwh);
    compact(st, br1);
    simLayer<1>(st, x, batch, w, pw, rotU, vwU, pco, pwh);
    compact(st, br2);
    simLayer<2>(st, x, batch, w, pw, rotU, vwU, pco, pwh);

    // per-leaf EV partials (trace over anc bits 8,9; Z-signs on bits 0..7)
    float acc[8];
#pragma unroll
    for (int q = 0; q < 8; ++q) acc[q] = 0.0f;
    for (int i = tid; i < 1024; i += NTH) {
        float2 a = st[IDX(i)];
        float p = a.x * a.x + a.y * a.y;
#pragma unroll
        for (int q = 0; q < 8; ++q) acc[q] += ((i >> q) & 1) ? -p : p;
    }
    const int wid = tid >> 5, lane = tid & 31;
#pragma unroll
    for (int q = 0; q < 8; ++q) {
        float v = acc[q];
#pragma unroll
        for (int o = 16; o > 0; o >>= 1) v += __shfl_down_sync(0xffffffffu, v, o);
        if (lane == 0) wsum[wid][q] = v;
    }
    __syncthreads();
    if (tid < 8) {
        float s = 0.0f;
#pragma unroll
        for (int wgi = 0; wgi < NTH / 32; ++wgi) s += wsum[wgi][tid];
        g_ev[blk * 8 + tid] = s;
    }

    // last CTA of this batch reduces the 16 branch partials.
    // Monotonic ticket (never reset) -> graph-replay safe: each launch adds
    // exactly 16 per batch, so old % 16 == 15 identifies this launch's last.
    __threadfence();
    __syncthreads();
    if (tid == 0) {
        unsigned int old = atomicAdd(&g_tk[batch], 1u);
        lastflag = ((old & 15u) == 15u);
    }
    __syncthreads();
    if (lastflag) {
        __threadfence();
        if (tid < 8) {
            float s = 0.0f;
#pragma unroll
            for (int k = 0; k < 16; ++k) s += g_ev[(batch * 16 + k) * 8 + tid];
            out[batch * 8 + tid] = s;
        }
    }
}

extern "C" void kernel_launch(void* const* d_in, const int* in_sizes, int n_in,
                              void* d_out, int out_size) {
    const float* x  = (const float*)d_in[0];   // (16, 8)
    const float* w  = (const float*)d_in[1];   // (3, 48)
    const float* pw = (const float*)d_in[2];   // (3, 2, 8)
    float* out = (float*)d_out;                // (16, 8)
    (void)in_sizes; (void)n_in; (void)out_size;

    qpie_all<<<256, NTH>>>(x, w, pw, out);
}

// round 15
// speedup vs baseline: 1.1635x; 1.1635x over previous
#include <cuda_runtime.h>

// QPIELayer single-kernel, register-resident state.
// 16-qubit circuit reduced to 10 live qubits (8 system + 2 ancilla); records
// are write-once / read-once-as-control and traced by the diagonal
// measurement, so each layer boundary is an incoherent 4-way branch split.
// 256 CTAs = one per (batch, layer1-branch, layer2-branch) leaf; each CTA
// redundantly recomputes layers 0/1 for its branch path.
//
// State layout (1024 amps per branch): amp index i = (a << 8) | tid, where
//   a    = ancilla bits (bit8 = a&1, bit9 = a&2)  -> register index r[a]
//   tid  bits 0..4 = lane bits  (gates via __shfl_xor)
//   tid  bits 5..7 = warp bits  (gates via conflict-free smem exchange)
// Ancilla block (H(x)H + CRZ diagonal) is pure register math.

#define NTH 256

__device__ float        g_ev[256 * 8];   // per-leaf EV partials
__device__ unsigned int g_tk[16];        // per-batch monotonic tickets

__device__ __forceinline__ float2 cmul(float2 a, float2 b) {
    return make_float2(a.x * b.x - a.y * b.y, a.x * b.y + a.y * b.x);
}
__device__ __forceinline__ float2 cmac(float2 a, float2 b, float2 c) {   // a*b + c
    return make_float2(fmaf(a.x, b.x, fmaf(-a.y, b.y, c.x)),
                       fmaf(a.x, b.y, fmaf( a.y, b.x, c.y)));
}
__device__ __forceinline__ float2 cconj(float2 a) { return make_float2(a.x, -a.y); }
__device__ __forceinline__ float2 cadd(float2 a, float2 b) { return make_float2(a.x + b.x, a.y + b.y); }
__device__ __forceinline__ float2 csub(float2 a, float2 b) { return make_float2(a.x - b.x, a.y - b.y); }
__device__ __forceinline__ float2 chalf(float2 a) { return make_float2(0.5f * a.x, 0.5f * a.y); }

__device__ __forceinline__ float2 shfl_xor2(float2 v, int m) {
    v.x = __shfl_xor_sync(0xffffffffu, v.x, m);
    v.y = __shfl_xor_sync(0xffffffffu, v.y, m);
    return v;
}

// ---- single-qubit gate on lane bit B (B <= 4), U = {u00,u01,u10,u11} -------
template<int B>
__device__ __forceinline__ void gate1_sh(float2* r, const float2* U) {
    const int bit = (threadIdx.x >> B) & 1;
    const float2 ua = bit ? U[3] : U[0];     // coef on own amp
    const float2 ub = bit ? U[2] : U[1];     // coef on partner amp
#pragma unroll
    for (int a = 0; a < 4; ++a) {
        float2 p = shfl_xor2(r[a], 1 << B);
        r[a] = cmac(ua, r[a], cmul(ub, p));
    }
}

// ---- three fused single-qubit gates on warp bits 5,6,7 (one smem exchange) -
__device__ __forceinline__ void gate3_high(float2* r, float2 (*buf)[NTH],
                                           const float2* U5, const float2* U6,
                                           const float2* U7) {
    const int tid = threadIdx.x;
    const int w = tid >> 5, lane = tid & 31;
    const int b5 = w & 1, b6 = (w >> 1) & 1, b7 = (w >> 2) & 1;
    float2 M[8];                              // own row of U7 (x) U6 (x) U5
#pragma unroll
    for (int wp = 0; wp < 8; ++wp) {
        float2 m = cmul(U5[b5 * 2 + (wp & 1)], U6[b6 * 2 + ((wp >> 1) & 1)]);
        M[wp] = cmul(m, U7[b7 * 2 + ((wp >> 2) & 1)]);
    }
#pragma unroll
    for (int a = 0; a < 4; ++a) buf[a][tid] = r[a];
    __syncthreads();
#pragma unroll
    for (int a = 0; a < 4; ++a) {
        float2 acc = make_float2(0.f, 0.f);
#pragma unroll
        for (int wp = 0; wp < 8; ++wp)
            acc = cmac(M[wp], buf[a][wp * 32 + lane], acc);
        r[a] = acc;
    }
    __syncthreads();
}

// ---- fused RZZ*RYY*RXX on (B1,B2): each amp mixes with ONE partner ---------
// pc = {K=cos((t1-t2)/2), Lc=-sin((t1-t2)/2), K2=cos((t1+t2)/2),
//       L2=sin((t1+t2)/2), ec=cos(t3/2), es=sin(t3/2)}
// parity 0 (00/11): o = (ec - i es) * (K*own + i*Lc*par)
// parity 1 (01/10): o = (ec + i es) * (K2*own - i*L2*par)
__device__ __forceinline__ void pair_core(float2* r, const float2* p,
                                          float Kc, float S, float2 ph) {
#pragma unroll
    for (int a = 0; a < 4; ++a) {
        float2 t = make_float2(Kc * r[a].x - S * p[a].y, Kc * r[a].y + S * p[a].x);
        r[a] = cmul(ph, t);
    }
}

template<int B1, int B2>
__device__ __forceinline__ void pair_sh(float2* r, const float* pc) {
    const int pr = ((threadIdx.x >> B1) ^ (threadIdx.x >> B2)) & 1;
    const float Kc = pr ? pc[2] : pc[0];
    const float S  = pr ? -pc[3] : pc[1];
    const float2 ph = make_float2(pc[4], pr ? pc[5] : -pc[5]);
    float2 p[4];
#pragma unroll
    for (int a = 0; a < 4; ++a) p[a] = shfl_xor2(r[a], (1 << B1) | (1 << B2));
    pair_core(r, p, Kc, S, ph);
}

template<int B1, int B2>
__device__ __forceinline__ void pair_sm(float2* r, float2 (*buf)[NTH], const float* pc) {
    const int tid = threadIdx.x;
    const int ptid = tid ^ ((1 << B1) | (1 << B2));
    const int pr = ((tid >> B1) ^ (tid >> B2)) & 1;
    const float Kc = pr ? pc[2] : pc[0];
    const float S  = pr ? -pc[3] : pc[1];
    const float2 ph = make_float2(pc[4], pr ? pc[5] : -pc[5]);
#pragma unroll
    for (int a = 0; a < 4; ++a) buf[a][tid] = r[a];
    __syncthreads();
    float2 p[4];
#pragma unroll
    for (int a = 0; a < 4; ++a) p[a] = buf[a][ptid];
    pair_core(r, p, Kc, S, ph);
    __syncthreads();
}

// ---- CCRX(pi/4): control anc regs in AM mask + tid bit B1; target lane bit B2
template<int B1, int B2, int AM>
__device__ __forceinline__ void ccrx_sh(float2* r) {
    const float cc = 0.92387953251128675613f;   // cos(pi/8)
    const float ss = 0.38268343236508977173f;   // sin(pi/8)
    const int ctrl = (threadIdx.x >> B1) & 1;
#pragma unroll
    for (int a = 0; a < 4; ++a) {
        if (AM & (1 << a)) {
            float2 p = shfl_xor2(r[a], 1 << B2);
            if (ctrl)
                r[a] = make_float2(cc * r[a].x + ss * p.y, cc * r[a].y - ss * p.x);
        }
    }
}

// ---- ancilla block, pure registers: (H(x)H), CRZ diag, (H(x)H if ODD) ------
template<int ODD>
__device__ __forceinline__ void anc_reg(float2* r, const float* pwh) {
    const int s = threadIdx.x;
    float2 v0 = chalf(cadd(cadd(r[0], r[1]), cadd(r[2], r[3])));
    float2 v1 = chalf(cadd(csub(r[0], r[1]), csub(r[2], r[3])));
    float2 v2 = chalf(csub(cadd(r[0], r[1]), cadd(r[2], r[3])));
    float2 v3 = chalf(cadd(csub(r[0], r[1]), csub(r[3], r[2])));
    float d0 = 0.0f, d1 = 0.0f;
#pragma unroll
    for (int j = 0; j < 8; ++j)
        if ((s >> j) & 1) { d0 += pwh[j]; d1 += pwh[8 + j]; }
    float sp, cp, sm, cm;
    sincosf(d0 + d1, &sp, &cp);
    sincosf(d0 - d1, &sm, &cm);
    float2 P = make_float2(cp, sp), M = make_float2(cm, sm);
    r[0] = cmul(cconj(P), v0);
    r[1] = cmul(M,        v1);
    r[2] = cmul(cconj(M), v2);
    r[3] = cmul(P,        v3);
    if (ODD) {
        float2 y0 = chalf(cadd(cadd(r[0], r[1]), cadd(r[2], r[3])));
        float2 y1 = chalf(cadd(csub(r[0], r[1]), csub(r[2], r[3])));
        float2 y2 = chalf(csub(cadd(r[0], r[1]), cadd(r[2], r[3])));
        float2 y3 = chalf(cadd(csub(r[0], r[1]), csub(r[3], r[2])));
        r[0] = y0; r[1] = y1; r[2] = y2; r[3] = y3;
    }
}

// ---- one full layer --------------------------------------------------------
template<int L>
__device__ __forceinline__ void simLayer(float2* r, float2 (*buf)[NTH],
                                         const float* x, int batch,
                                         const float* w, const float* pw,
                                         float2 (*rotU)[4], float2 (*vwU)[4],
                                         float (*pco)[6], float* pwh) {
    const float* wl  = w  + L * 48;
    const float* pwl = pw + L * 16;
    const int tid = threadIdx.x;
    const float R = 0.70710678118654752440f;

    if (tid < 8) {                               // per-qubit rot (RY even / RX odd)
        float s, c;
        sincosf(0.5f * x[batch * 8 + tid], &s, &c);
        float2 u00, u01, u10, u11;
        if ((L & 1) == 0) {
            u00 = make_float2(c, 0); u01 = make_float2(-s, 0);
            u10 = make_float2(s, 0); u11 = make_float2(c, 0);
        } else {
            u00 = make_float2(c, 0); u01 = make_float2(0, -s);
            u10 = make_float2(0, -s); u11 = make_float2(c, 0);
        }
        if (L == 0) {   // fold initial H: U <- U @ H
            float2 v00 = make_float2(R * (u00.x + u01.x), R * (u00.y + u01.y));
            float2 v01 = make_float2(R * (u00.x - u01.x), R * (u00.y - u01.y));
            float2 v10 = make_float2(R * (u10.x + u11.x), R * (u10.y + u11.y));
            float2 v11 = make_float2(R * (u10.x - u11.x), R * (u10.y - u11.y));
            u00 = v00; u01 = v01; u10 = v10; u11 = v11;
        }
        rotU[tid][0] = u00; rotU[tid][1] = u01; rotU[tid][2] = u10; rotU[tid][3] = u11;
    } else if (tid < 16) {                       // fused RZ*RY*RX (vw block)
        int q = tid - 8;
        float t1 = wl[24 + 3 * q], t2 = wl[25 + 3 * q], t3 = wl[26 + 3 * q];
        float s1, c1, s2, c2, es, ec;
        sincosf(0.5f * t1, &s1, &c1);
        sincosf(0.5f * t2, &s2, &c2);
        sincosf(0.5f * t3, &es, &ec);
        float2 a00 = make_float2(c1 * c2,  s1 * s2);
        float2 a01 = make_float2(-s2 * c1, -c2 * s1);
        float2 a10 = make_float2( s2 * c1, -c2 * s1);
        float2 a11 = make_float2(c1 * c2, -s1 * s2);
        float2 e = make_float2(ec, -es);
        vwU[q][0] = cmul(e, a00); vwU[q][1] = cmul(e, a01);
        vwU[q][2] = cmul(cconj(e), a10); vwU[q][3] = cmul(cconj(e), a11);
    } else if (tid < 23) {                       // pair-gate coefficients
        int i = tid - 16;
        float t1 = wl[3 * i], t2 = wl[3 * i + 1], t3 = wl[3 * i + 2];
        float sd, cd, s2, c2, es, ec;
        sincosf(0.5f * (t1 - t2), &sd, &cd);
        sincosf(0.5f * (t1 + t2), &s2, &c2);
        sincosf(0.5f * t3, &es, &ec);
        pco[i][0] = cd; pco[i][1] = -sd; pco[i][2] = c2; pco[i][3] = s2;
        pco[i][4] = ec; pco[i][5] = es;
    } else if (tid >= 32 && tid < 48) {
        pwh[tid - 32] = 0.5f * pwl[tid - 32];
    }
    __syncthreads();

    // per-qubit rotations (all single-qubit gates commute)
    gate1_sh<0>(r, rotU[0]);
    gate1_sh<1>(r, rotU[1]);
    gate1_sh<2>(r, rotU[2]);
    gate1_sh<3>(r, rotU[3]);
    gate1_sh<4>(r, rotU[4]);
    gate3_high(r, buf, rotU[5], rotU[6], rotU[7]);

    anc_reg<(L & 1)>(r, pwh);

    // entangling pairs: disjoint group first (order-safe), then offset group
    pair_sh<0, 1>(r, pco[0]);  ccrx_sh<0, 1, 10>(r);   // anc bit8 -> regs {1,3}
    pair_sh<2, 3>(r, pco[1]);  ccrx_sh<2, 3, 12>(r);   // anc bit9 -> regs {2,3}
    pair_sm<4, 5>(r, buf, pco[2]);
    pair_sm<6, 7>(r, buf, pco[3]);
    pair_sh<1, 2>(r, pco[4]);
    pair_sh<3, 4>(r, pco[5]);
    pair_sm<5, 6>(r, buf, pco[6]);

    // fused RZ*RY*RX per system qubit
    gate1_sh<0>(r, vwU[0]);
    gate1_sh<1>(r, vwU[1]);
    gate1_sh<2>(r, vwU[2]);
    gate1_sh<3>(r, vwU[3]);
    gate1_sh<4>(r, vwU[4]);
    gate3_high(r, buf, vwU[5], vwU[6], vwU[7]);
}

__global__ void __launch_bounds__(NTH)
qpie_all(const float* __restrict__ x, const float* __restrict__ w,
         const float* __restrict__ pw, float* __restrict__ out) {
    __shared__ float2 buf[4][NTH];
    __shared__ float2 rotU[8][4];
    __shared__ float2 vwU[8][4];
    __shared__ float  pco[7][6];
    __shared__ float  pwh[16];
    __shared__ float  wsum[NTH / 32][8];
    __shared__ unsigned int lastflag;

    const int blk = blockIdx.x, tid = threadIdx.x;
    const int batch = blk >> 4, br1 = (blk >> 2) & 3, br2 = blk & 3;

    float2 r[4];
    r[0] = make_float2(tid == 0 ? 1.0f : 0.0f, 0.0f);
    r[1] = r[2] = r[3] = make_float2(0.0f, 0.0f);

    simLayer<0>(r, buf, x, batch, w, pw, rotU, vwU, pco, pwh);
    // compact: keep ancilla pattern br1, reset ancillas to |00>
    r[0] = r[br1]; r[1] = r[2] = r[3] = make_float2(0.0f, 0.0f);
    simLayer<1>(r, buf, x, batch, w, pw, rotU, vwU, pco, pwh);
    r[0] = r[br2]; r[1] = r[2] = r[3] = make_float2(0.0f, 0.0f);
    simLayer<2>(r, buf, x, batch, w, pw, rotU, vwU, pco, pwh);

    // per-leaf EV partials: signs depend only on tid bits 0..7
    float tot = 0.0f;
#pragma unroll
    for (int a = 0; a < 4; ++a)
        tot += r[a].x * r[a].x + r[a].y * r[a].y;

    const int wid = tid >> 5, lane = tid & 31;
#pragma unroll
    for (int q = 0; q < 8; ++q) {
        float v = ((tid >> q) & 1) ? -tot : tot;
#pragma unroll
        for (int o = 16; o > 0; o >>= 1) v += __shfl_down_sync(0xffffffffu, v, o);
        if (lane == 0) wsum[wid][q] = v;
    }
    __syncthreads();
    if (tid < 8) {
        float s = 0.0f;
#pragma unroll
        for (int wgi = 0; wgi < NTH / 32; ++wgi) s += wsum[wgi][tid];
        g_ev[blk * 8 + tid] = s;
    }

    // last CTA per batch reduces the 16 branch partials (fixed order ->
    // deterministic). Monotonic ticket, never reset -> graph-replay safe.
    __threadfence();
    __syncthreads();
    if (tid == 0) {
        unsigned int old = atomicAdd(&g_tk[batch], 1u);
        lastflag = ((old & 15u) == 15u);
    }
    __syncthreads();
    if (lastflag) {
        __threadfence();
        if (tid < 8) {
            float s = 0.0f;
#pragma unroll
            for (int k = 0; k < 16; ++k) s += g_ev[(batch * 16 + k) * 8 + tid];
            out[batch * 8 + tid] = s;
        }
    }
}

extern "C" void kernel_launch(void* const* d_in, const int* in_sizes, int n_in,
                              void* d_out, int out_size) {
    const float* x  = (const float*)d_in[0];   // (16, 8)
    const float* w  = (const float*)d_in[1];   // (3, 48)
    const float* pw = (const float*)d_in[2];   // (3, 2, 8)
    float* out = (float*)d_out;                // (16, 8)
    (void)in_sizes; (void)n_in; (void)out_size;

    qpie_all<<<256, NTH>>>(x, w, pw, out);
}